// round 10
// baseline (speedup 1.0000x reference)
#include <cuda_runtime.h>
#include <cuda_bf16.h>
#include <cstdint>

// ---------------------------------------------------------------- constants
constexpr int MTOK = 8192, DIN = 4096, DOUT = 4096;
constexpr int E = 8, DK = 32, R = 16;
constexpr int NPROJ = 640, NPROJ_PAD = 768;
constexpr int GEXT  = 192;                 // ext cols per panel (128 lora + 1 bias + pad)
constexpr int GLD   = 2 * GEXT;            // 384: [hi(192) | lo(192)] row stride

// ---------------------------------------------------------------- scratch
__device__ __align__(1024) __nv_bfloat16 g_Gx[(size_t)MTOK * GLD];   // routed ext (hi|lo)
__device__ __align__(1024) __nv_bfloat16 g_B2[(size_t)DOUT * GLD];   // B2 ext (hi|lo)
__device__ __align__(1024) __nv_bfloat16 g_Pp[(size_t)NPROJ_PAD * DIN];
__device__ __align__(1024) float         g_P [(size_t)MTOK * NPROJ_PAD];

// ---------------------------------------------------------------- ptx utils
__device__ __forceinline__ uint32_t smem_u32(const void* p) {
    uint32_t a;
    asm("{ .reg .u64 t; cvta.to.shared.u64 t, %1; cvt.u32.u64 %0, t; }" : "=r"(a) : "l"(p));
    return a;
}
__device__ __forceinline__ uint32_t ctarank() {
    uint32_t r; asm("mov.u32 %0, %%cluster_ctarank;" : "=r"(r)); return r;
}
__device__ __forceinline__ void cluster_sync() {
    asm volatile("barrier.cluster.arrive.aligned;" ::: "memory");
    asm volatile("barrier.cluster.wait.aligned;" ::: "memory");
}
__device__ __forceinline__ void mbar_init(uint32_t a, uint32_t c) {
    asm volatile("mbarrier.init.shared.b64 [%0], %1;" :: "r"(a), "r"(c) : "memory");
}
__device__ __forceinline__ void mbar_inval(uint32_t a) {
    asm volatile("mbarrier.inval.shared.b64 [%0];" :: "r"(a) : "memory");
}
__device__ __forceinline__ void mbar_arrive_rank0(uint32_t a) {
    asm volatile("{ .reg .b32 ra; mapa.shared::cluster.u32 ra, %0, 0;"
                 " mbarrier.arrive.shared::cluster.b64 _, [ra]; }" :: "r"(a) : "memory");
}
__device__ __forceinline__ void mbar_wait(uint32_t a, uint32_t parity) {
    asm volatile("{ .reg .pred P;\n"
                 "W%=: mbarrier.try_wait.parity.acquire.cta.shared::cta.b64 P, [%0], %1, 0x989680;\n"
                 "@P bra D%=;\n bra W%=;\nD%=: }"
                 :: "r"(a), "r"(parity) : "memory");
}
__device__ __forceinline__ void fence_async() {
    asm volatile("fence.proxy.async.shared::cta;" ::: "memory");
}
constexpr uint64_t DESC_BASE = (2ull<<61) | (1ull<<46) | (64ull<<32) | (1ull<<16);
__device__ __forceinline__ uint64_t mk_desc(uint32_t a) { return DESC_BASE | ((a >> 4) & 0x3FFF); }
constexpr uint32_t IDESC = (1u<<4) | (1u<<7) | (1u<<10) | ((256/8)<<17) | ((256/16)<<24);

__device__ __forceinline__ void mma_cg2(uint32_t d, uint64_t ad, uint64_t bd, uint32_t en) {
    asm volatile("{ .reg .pred p; setp.ne.u32 p, %5, 0;\n"
                 "tcgen05.mma.cta_group::2.kind::f16 [%0], %1, %2, %3,"
                 " {%4,%4,%4,%4,%4,%4,%4,%4}, p; }"
                 :: "r"(d), "l"(ad), "l"(bd), "r"(IDESC), "r"(0u), "r"(en) : "memory");
}

// ---------------------------------------------------------------- split helpers
__device__ __forceinline__ void split2(float v, __nv_bfloat16& hi, __nv_bfloat16& lo) {
    hi = __float2bfloat16(v);
    lo = __float2bfloat16(v - __bfloat162float(hi));
}
__device__ __forceinline__ uint32_t pack2(__nv_bfloat16 a, __nv_bfloat16 b) {
    __nv_bfloat162 t(a, b);
    return *reinterpret_cast<uint32_t*>(&t);
}

// fp32 128x64 tile -> swizzled bf16 hi+lo tiles (256 threads)
__device__ __forceinline__ void load_convert_tile(uint32_t dhi, uint32_t dlo,
                                                  const float* __restrict__ src,
                                                  int ld, int tid) {
    const int r0 = tid >> 4, c4 = (tid & 15) * 4;
    float4 v[8];
#pragma unroll
    for (int p = 0; p < 8; p++)
        v[p] = *reinterpret_cast<const float4*>(src + (size_t)(r0 + p * 16) * ld + c4);
#pragma unroll
    for (int p = 0; p < 8; p++) {
        uint32_t off = (uint32_t)((r0 + p * 16) * 128 + (tid & 15) * 8);
        uint32_t sw = off ^ ((off >> 3) & 0x70);
        __nv_bfloat16 h0,l0,h1,l1,h2,l2,h3,l3;
        split2(v[p].x,h0,l0); split2(v[p].y,h1,l1); split2(v[p].z,h2,l2); split2(v[p].w,h3,l3);
        asm volatile("st.shared.v2.u32 [%0], {%1,%2};"
                     :: "r"(dhi + sw), "r"(pack2(h0,h1)), "r"(pack2(h2,h3)));
        asm volatile("st.shared.v2.u32 [%0], {%1,%2};"
                     :: "r"(dlo + sw), "r"(pack2(l0,l1)), "r"(pack2(l2,l3)));
    }
}

// fp32 128x64 tile -> swizzled bf16 hi tile only
__device__ __forceinline__ void load_convert_hi(uint32_t dhi, const float* __restrict__ src,
                                                int ld, int tid) {
    const int r0 = tid >> 4, c4 = (tid & 15) * 4;
    float4 v[8];
#pragma unroll
    for (int p = 0; p < 8; p++)
        v[p] = *reinterpret_cast<const float4*>(src + (size_t)(r0 + p * 16) * ld + c4);
#pragma unroll
    for (int p = 0; p < 8; p++) {
        uint32_t off = (uint32_t)((r0 + p * 16) * 128 + (tid & 15) * 8);
        uint32_t sw = off ^ ((off >> 3) & 0x70);
        asm volatile("st.shared.v2.u32 [%0], {%1,%2};"
                     :: "r"(dhi + sw),
                        "r"(pack2(__float2bfloat16(v[p].x), __float2bfloat16(v[p].y))),
                        "r"(pack2(__float2bfloat16(v[p].z), __float2bfloat16(v[p].w))));
    }
}

// bf16 128x64 tile raw copy -> swizzled smem
__device__ __forceinline__ void copy_tile_bf16(uint32_t dst, const __nv_bfloat16* __restrict__ src,
                                               int ld, int tid) {
    const int r0 = tid >> 3, u = tid & 7;
#pragma unroll
    for (int p = 0; p < 4; p++) {
        int r = r0 + p * 32;
        uint4 v = *reinterpret_cast<const uint4*>(src + (size_t)r * ld + u * 8);
        uint32_t off = (uint32_t)(r * 128 + u * 16);
        uint32_t sw = off ^ ((off >> 3) & 0x70);
        asm volatile("st.shared.v4.u32 [%0], {%1,%2,%3,%4};"
                     :: "r"(dst + sw), "r"(v.x), "r"(v.y), "r"(v.z), "r"(v.w));
    }
}

// ---------------------------------------------------------------- pack kernels
__global__ void split_proj_kernel(const float* __restrict__ Wq,
                                  const float* __restrict__ Wk,
                                  const float* __restrict__ A) {
    size_t t = (size_t)blockIdx.x * 256 + threadIdx.x;
    if (t >= (size_t)NPROJ_PAD * DIN / 4) return;
    int row = (int)(t / (DIN / 4)), col = (int)(t % (DIN / 4)) * 4;
    float4 v = make_float4(0.f, 0.f, 0.f, 0.f);
    if (row < 256)      v = *reinterpret_cast<const float4*>(Wq + (size_t)row * DIN + col);
    else if (row < 512) v = *reinterpret_cast<const float4*>(Wk + (size_t)(row - 256) * DIN + col);
    else if (row < 640) v = *reinterpret_cast<const float4*>(A  + (size_t)(row - 512) * DIN + col);
    *reinterpret_cast<uint2*>(g_Pp + (size_t)row * DIN + col) =
        make_uint2(pack2(__float2bfloat16(v.x), __float2bfloat16(v.y)),
                   pack2(__float2bfloat16(v.z), __float2bfloat16(v.w)));
}

// B2[o,j]: j<128 -> Bm[e,o,r]; j==128 -> b[o]; else 0. hi at j, lo at 192+j.
__global__ void pack_b2_kernel(const float* __restrict__ Bm, const float* __restrict__ b) {
    int idx = blockIdx.x * 256 + threadIdx.x;
    if (idx >= DOUT * GEXT) return;
    int o = idx / GEXT, j = idx - o * GEXT;
    float v = 0.f;
    if (j < E * R) { int e = j >> 4, r = j & 15; v = Bm[((size_t)e * DOUT + o) * R + r]; }
    else if (j == E * R) v = b[o];
    __nv_bfloat16 hi, lo; split2(v, hi, lo);
    g_B2[(size_t)o * GLD + j] = hi;
    g_B2[(size_t)o * GLD + GEXT + j] = lo;
}

// ---------------------------------------------------------------- routing
__global__ void routing_kernel() {
    int warp = (blockIdx.x * blockDim.x + threadIdx.x) >> 5;
    int lane = threadIdx.x & 31;
    if (warp >= MTOK) return;
    const float* Pt = g_P + (size_t)warp * NPROJ_PAD;
    float s[E];
#pragma unroll
    for (int e = 0; e < E; e++) {
        float p = Pt[e * DK + lane] * Pt[E * DK + e * DK + lane];
#pragma unroll
        for (int o = 16; o > 0; o >>= 1) p += __shfl_xor_sync(0xffffffffu, p, o);
        s[e] = p * 0.17677669529663687f;
    }
    float m = s[0];
#pragma unroll
    for (int e = 1; e < E; e++) m = fmaxf(m, s[e]);
    float Z = 0.f;
#pragma unroll
    for (int e = 0; e < E; e++) { s[e] = __expf(s[e] - m); Z += s[e]; }
    float inv = 1.f / Z;

    __nv_bfloat16* Gt = g_Gx + (size_t)warp * GLD;
#pragma unroll
    for (int j = lane; j < GEXT; j += 32) {
        float g = 0.f;
        if (j < E * R)       g = s[j >> 4] * inv * Pt[2 * E * DK + j];
        else if (j == E * R) g = 1.0f;
        __nv_bfloat16 hi, lo; split2(g, hi, lo);
        Gt[j] = hi;
        Gt[GEXT + j] = lo;
    }
}

// ---------------------------------------------------------------- proj GEMM (fused convert, hi only)
__global__ void __cluster_dims__(2, 1, 1) __launch_bounds__(256, 1)
gemm_proj_kernel(const float* __restrict__ xg) {
#if defined(__CUDA_ARCH_FEAT_SM103_ALL)
    constexpr int NST = 2, NCH = DIN / 64, STAGE = 32768;   // A 16KB + B 16KB
    constexpr int SLAST = (NCH - 1) & (NST - 1);            // 1
    constexpr uint32_t FINPAR = (((NCH - 1 - SLAST) / NST + 1) - 1) & 1;  // 1

    extern __shared__ char smem[];
    const uint32_t sbase = smem_u32(smem);
    const int tid = threadIdx.x, wid = tid >> 5, lane = tid & 31;
    const uint32_t rank = ctarank();
    const int n_tile = blockIdx.x >> 1, m_tile = blockIdx.y;
    const uint32_t FULL0 = sbase + 8, MMAB0 = sbase + 40;

    if (tid == 0)
        for (int s = 0; s < NST; s++) { mbar_init(FULL0 + s * 8, 2); mbar_init(MMAB0 + s * 8, 1); }
    if (wid == 0)
        asm volatile("tcgen05.alloc.cta_group::2.sync.aligned.shared::cta.b32 [%0], %1;"
                     :: "r"(sbase), "r"(512) : "memory");
    __syncthreads();
    uint32_t tmem;
    asm volatile("ld.shared.b32 %0, [%1];" : "=r"(tmem) : "r"(sbase));
    cluster_sync();

    const float* Arow = xg + (size_t)(m_tile * 256 + rank * 128) * DIN;
    const __nv_bfloat16* Brow = g_Pp + (size_t)(n_tile * 256 + rank * 128) * DIN;

    auto fill = [&](int chunk) {
        const uint32_t st = sbase + 1024 + (chunk & (NST - 1)) * STAGE;
        load_convert_hi(st, Arow + chunk * 64, DIN, tid);
        copy_tile_bf16(st + 16384, Brow + chunk * 64, DIN, tid);
    };

    uint32_t fph[NST] = {}, mph[NST] = {};
    fill(0);
    for (int i = 0; i < NCH; i++) {
        const int s = i & (NST - 1);
        fence_async();
        __syncthreads();
        if (tid == 0) mbar_arrive_rank0(FULL0 + s * 8);
        if (rank == 0 && tid == 0) {
            mbar_wait(FULL0 + s * 8, fph[s]); fph[s] ^= 1;
            const uint32_t st = sbase + 1024 + s * STAGE;
            uint64_t ad = mk_desc(st), bd = mk_desc(st + 16384);
#pragma unroll
            for (int kk = 0; kk < 4; kk++)
                mma_cg2(tmem, ad + kk * 2, bd + kk * 2, (i > 0) || (kk > 0));
            asm volatile("tcgen05.commit.cta_group::2.mbarrier::arrive::one.shared::cluster.multicast::cluster.b64 [%0], %1;"
                         :: "r"(MMAB0 + s * 8), "h"((uint16_t)3) : "memory");
        }
        const int j = i + 1;
        if (j < NCH) {
            const int s2 = j & (NST - 1);
            if (j >= NST) { mbar_wait(MMAB0 + s2 * 8, mph[s2]); mph[s2] ^= 1; }
            fill(j);
        }
    }
    mbar_wait(MMAB0 + SLAST * 8, FINPAR);
    asm volatile("tcgen05.fence::after_thread_sync;" ::: "memory");

    {
        const int gm = m_tile * 256 + (int)rank * 128 + (wid & 3) * 32 + lane;
        float* crow = g_P + (size_t)gm * NPROJ_PAD + n_tile * 256 + (wid >> 2) * 128;
        const uint32_t cb0 = tmem + (uint32_t)((wid >> 2) * 128);
#pragma unroll
        for (int cb = 0; cb < 128; cb += 32) {
            uint32_t d[32];
            asm volatile("tcgen05.ld.sync.aligned.32x32b.x32.b32 "
                "{%0,%1,%2,%3,%4,%5,%6,%7,%8,%9,%10,%11,%12,%13,%14,%15,"
                "%16,%17,%18,%19,%20,%21,%22,%23,%24,%25,%26,%27,%28,%29,%30,%31}, [%32];"
                : "=r"(d[0]),"=r"(d[1]),"=r"(d[2]),"=r"(d[3]),"=r"(d[4]),"=r"(d[5]),"=r"(d[6]),"=r"(d[7]),
                  "=r"(d[8]),"=r"(d[9]),"=r"(d[10]),"=r"(d[11]),"=r"(d[12]),"=r"(d[13]),"=r"(d[14]),"=r"(d[15]),
                  "=r"(d[16]),"=r"(d[17]),"=r"(d[18]),"=r"(d[19]),"=r"(d[20]),"=r"(d[21]),"=r"(d[22]),"=r"(d[23]),
                  "=r"(d[24]),"=r"(d[25]),"=r"(d[26]),"=r"(d[27]),"=r"(d[28]),"=r"(d[29]),"=r"(d[30]),"=r"(d[31])
                : "r"(cb0 + cb));
            asm volatile("tcgen05.wait::ld.sync.aligned;" ::: "memory");
#pragma unroll
            for (int c = 0; c < 32; c += 4)
                *reinterpret_cast<float4*>(crow + cb + c) =
                    make_float4(__uint_as_float(d[c]), __uint_as_float(d[c+1]),
                                __uint_as_float(d[c+2]), __uint_as_float(d[c+3]));
        }
    }
    __syncthreads();
    if (tid == 0) {
        for (int s = 0; s < NST; s++) { mbar_inval(FULL0 + s * 8); mbar_inval(MMAB0 + s * 8); }
    }
    __syncthreads();
    if (wid == 0) {
        asm volatile("tcgen05.relinquish_alloc_permit.cta_group::2.sync.aligned;");
        asm volatile("tcgen05.dealloc.cta_group::2.sync.aligned.b32 %0, %1;" :: "r"(tmem), "r"(512));
    }
    cluster_sync();
#endif
}

// ---------------------------------------------------------------- main GEMM (fused convert, 3-product)
__global__ void __cluster_dims__(2, 1, 1) __launch_bounds__(256, 1)
gemm_main_kernel(const float* __restrict__ xg, const float* __restrict__ Wg,
                 float* __restrict__ Cg) {
#if defined(__CUDA_ARCH_FEAT_SM103_ALL)
    constexpr int NST = 2;
    constexpr int NCH = DIN / 64 + GEXT / 64;       // 64 + 3 = 67
    constexpr int STAGE = 98304;                    // A 32KB + B 64KB
    constexpr int A_HI = 0, A_LO = 16384, B_HI = 32768, B_LO = 65536;
    constexpr int SLAST = (NCH - 1) & (NST - 1);    // 0
    constexpr uint32_t FINPAR = (((NCH - 1 - SLAST) / NST + 1) - 1) & 1;  // 1

    extern __shared__ char smem[];
    const uint32_t sbase = smem_u32(smem);
    const int tid = threadIdx.x, wid = tid >> 5, lane = tid & 31;
    const uint32_t rank = ctarank();
    const int n_tile = blockIdx.x >> 1, m_tile = blockIdx.y;
    const uint32_t FULL0 = sbase + 8, MMAB0 = sbase + 40;

    if (tid == 0)
        for (int s = 0; s < NST; s++) { mbar_init(FULL0 + s * 8, 2); mbar_init(MMAB0 + s * 8, 1); }
    if (wid == 0)
        asm volatile("tcgen05.alloc.cta_group::2.sync.aligned.shared::cta.b32 [%0], %1;"
                     :: "r"(sbase), "r"(512) : "memory");
    __syncthreads();
    uint32_t tmem;
    asm volatile("ld.shared.b32 %0, [%1];" : "=r"(tmem) : "r"(sbase));
    cluster_sync();

    const int arow0 = m_tile * 256 + (int)rank * 128;
    const int brow0 = n_tile * 512 + (int)rank * 128;
    const float* Arow = xg + (size_t)arow0 * DIN;
    const float* Brow = Wg + (size_t)brow0 * DIN;
    const __nv_bfloat16* Aext = g_Gx + (size_t)arow0 * GLD;
    const __nv_bfloat16* Bext = g_B2 + (size_t)brow0 * GLD;

    auto fill = [&](int chunk) {
        const uint32_t st = sbase + 1024 + (chunk & (NST - 1)) * STAGE;
        if (chunk < 64) {
            const int kb = chunk * 64;
            load_convert_tile(st + A_HI, st + A_LO, Arow + kb, DIN, tid);
            load_convert_tile(st + B_HI, st + B_LO, Brow + kb, DIN, tid);
            load_convert_tile(st + B_HI + 16384, st + B_LO + 16384,
                              Brow + (size_t)256 * DIN + kb, DIN, tid);
        } else {
            const int cb = (chunk - 64) * 64;
            copy_tile_bf16(st + A_HI, Aext + cb, GLD, tid);
            copy_tile_bf16(st + A_LO, Aext + GEXT + cb, GLD, tid);
            copy_tile_bf16(st + B_HI, Bext + cb, GLD, tid);
            copy_tile_bf16(st + B_LO, Bext + GEXT + cb, GLD, tid);
            copy_tile_bf16(st + B_HI + 16384, Bext + (size_t)256 * GLD + cb, GLD, tid);
            copy_tile_bf16(st + B_LO + 16384, Bext + (size_t)256 * GLD + GEXT + cb, GLD, tid);
        }
    };

    uint32_t fph[NST] = {}, mph[NST] = {};
    fill(0);
    for (int i = 0; i < NCH; i++) {
        const int s = i & (NST - 1);
        fence_async();
        __syncthreads();
        if (tid == 0) mbar_arrive_rank0(FULL0 + s * 8);
        if (rank == 0 && tid == 0) {
            mbar_wait(FULL0 + s * 8, fph[s]); fph[s] ^= 1;
            const uint32_t st = sbase + 1024 + s * STAGE;
            uint64_t ahi = mk_desc(st + A_HI), alo = mk_desc(st + A_LO);
#pragma unroll
            for (int h = 0; h < 2; h++) {
                uint64_t bhi = mk_desc(st + B_HI + h * 16384);
                uint64_t blo = mk_desc(st + B_LO + h * 16384);
                uint32_t dh = tmem + h * 256;
#pragma unroll
                for (int kk = 0; kk < 4; kk++) {
                    uint32_t en = ((i > 0) || (kk > 0)) ? 1u : 0u;   // first MMA per half inits acc
                    mma_cg2(dh, ahi + kk * 2, bhi + kk * 2, en);
                    mma_cg2(dh, alo + kk * 2, bhi + kk * 2, 1u);
                    mma_cg2(dh, ahi + kk * 2, blo + kk * 2, 1u);
                }
            }
            asm volatile("tcgen05.commit.cta_group::2.mbarrier::arrive::one.shared::cluster.multicast::cluster.b64 [%0], %1;"
                         :: "r"(MMAB0 + s * 8), "h"((uint16_t)3) : "memory");
        }
        const int j = i + 1;
        if (j < NCH) {
            const int s2 = j & (NST - 1);
            if (j >= NST) { mbar_wait(MMAB0 + s2 * 8, mph[s2]); mph[s2] ^= 1; }
            fill(j);
        }
    }
    mbar_wait(MMAB0 + SLAST * 8, FINPAR);
    asm volatile("tcgen05.fence::after_thread_sync;" ::: "memory");

    // epilogue
    {
        const int gm = arow0 + (wid & 3) * 32 + lane;
        float* crow = Cg + (size_t)gm * DOUT + n_tile * 512 + (wid >> 2) * 256;
        const uint32_t cb0 = tmem + (uint32_t)((wid >> 2) * 256);
#pragma unroll
        for (int cb = 0; cb < 256; cb += 32) {
            uint32_t d[32];
            asm volatile("tcgen05.ld.sync.aligned.32x32b.x32.b32 "
                "{%0,%1,%2,%3,%4,%5,%6,%7,%8,%9,%10,%11,%12,%13,%14,%15,"
                "%16,%17,%18,%19,%20,%21,%22,%23,%24,%25,%26,%27,%28,%29,%30,%31}, [%32];"
                : "=r"(d[0]),"=r"(d[1]),"=r"(d[2]),"=r"(d[3]),"=r"(d[4]),"=r"(d[5]),"=r"(d[6]),"=r"(d[7]),
                  "=r"(d[8]),"=r"(d[9]),"=r"(d[10]),"=r"(d[11]),"=r"(d[12]),"=r"(d[13]),"=r"(d[14]),"=r"(d[15]),
                  "=r"(d[16]),"=r"(d[17]),"=r"(d[18]),"=r"(d[19]),"=r"(d[20]),"=r"(d[21]),"=r"(d[22]),"=r"(d[23]),
                  "=r"(d[24]),"=r"(d[25]),"=r"(d[26]),"=r"(d[27]),"=r"(d[28]),"=r"(d[29]),"=r"(d[30]),"=r"(d[31])
                : "r"(cb0 + cb));
            asm volatile("tcgen05.wait::ld.sync.aligned;" ::: "memory");
#pragma unroll
            for (int c = 0; c < 32; c += 4)
                *reinterpret_cast<float4*>(crow + cb + c) =
                    make_float4(__uint_as_float(d[c]), __uint_as_float(d[c+1]),
                                __uint_as_float(d[c+2]), __uint_as_float(d[c+3]));
        }
    }
    __syncthreads();
    if (tid == 0) {
        for (int s = 0; s < NST; s++) { mbar_inval(FULL0 + s * 8); mbar_inval(MMAB0 + s * 8); }
    }
    __syncthreads();
    if (wid == 0) {
        asm volatile("tcgen05.relinquish_alloc_permit.cta_group::2.sync.aligned;");
        asm volatile("tcgen05.dealloc.cta_group::2.sync.aligned.b32 %0, %1;" :: "r"(tmem), "r"(512));
    }
    cluster_sync();
#endif
}

// ---------------------------------------------------------------- launch
// Inputs (metadata order): x, W, b, Wq, Wk, A, Bm
extern "C" void kernel_launch(void* const* d_in, const int* in_sizes, int n_in,
                              void* d_out, int out_size) {
    const float* x  = (const float*)d_in[0];
    const float* W  = (const float*)d_in[1];
    const float* b  = (const float*)d_in[2];
    const float* Wq = (const float*)d_in[3];
    const float* Wk = (const float*)d_in[4];
    const float* A  = (const float*)d_in[5];
    const float* Bm = (const float*)d_in[6];
    float* out = (float*)d_out;

    constexpr int SMEM0 = 1024 + 2 * 32768;    // 66560
    constexpr int SMEM1 = 1024 + 2 * 98304;    // 197632
    cudaFuncSetAttribute(gemm_proj_kernel, cudaFuncAttributeMaxDynamicSharedMemorySize, SMEM0);
    cudaFuncSetAttribute(gemm_main_kernel, cudaFuncAttributeMaxDynamicSharedMemorySize, SMEM1);

    split_proj_kernel<<<(int)(((size_t)NPROJ_PAD * DIN / 4 + 255) / 256), 256>>>(Wq, Wk, A);
    pack_b2_kernel   <<<(DOUT * GEXT + 255) / 256, 256>>>(Bm, b);

    // projections P = x_hi @ [Wq;Wk;A]_hi^T  (fused fp32->bf16 convert)
    gemm_proj_kernel<<<dim3(2 * (NPROJ_PAD / 256), MTOK / 256), 256, SMEM0>>>(x);

    // routing -> G ext panels (hi|lo) in g_Gx
    routing_kernel<<<(MTOK * 32) / 256, 256>>>();

    // out = x @ W^T + G @ B2^T (+bias): fused-convert dedup 3-product GEMM
    gemm_main_kernel<<<dim3(2 * (DOUT / 512), MTOK / 256), 256, SMEM1>>>(x, W, out);
}

// round 11
// speedup vs baseline: 1.1010x; 1.1010x over previous
#include <cuda_runtime.h>
#include <cuda_bf16.h>
#include <cstdint>

// ---------------------------------------------------------------- constants
constexpr int MTOK = 8192, DIN = 4096, DOUT = 4096;
constexpr int E = 8, DK = 32, R = 16;
constexpr int NPROJ = 640, NPROJ_PAD = 768;
constexpr int GEXT  = 192;                 // ext cols per panel (128 lora + 1 bias + pad)
constexpr int GLD   = 2 * GEXT;            // 384: [hi(192) | lo(192)] row stride

// ---------------------------------------------------------------- scratch
__device__ __align__(1024) __nv_bfloat16 g_Gx[(size_t)MTOK * GLD];   // routed ext (hi|lo)
__device__ __align__(1024) __nv_bfloat16 g_B2[(size_t)DOUT * GLD];   // B2 ext (hi|lo)
__device__ __align__(1024) __nv_bfloat16 g_Pp[(size_t)NPROJ_PAD * DIN];
__device__ __align__(1024) float         g_P [(size_t)MTOK * NPROJ_PAD];

// ---------------------------------------------------------------- ptx utils
__device__ __forceinline__ uint32_t smem_u32(const void* p) {
    uint32_t a;
    asm("{ .reg .u64 t; cvta.to.shared.u64 t, %1; cvt.u32.u64 %0, t; }" : "=r"(a) : "l"(p));
    return a;
}
__device__ __forceinline__ uint32_t ctarank() {
    uint32_t r; asm("mov.u32 %0, %%cluster_ctarank;" : "=r"(r)); return r;
}
__device__ __forceinline__ void cluster_sync() {
    asm volatile("barrier.cluster.arrive.aligned;" ::: "memory");
    asm volatile("barrier.cluster.wait.aligned;" ::: "memory");
}
__device__ __forceinline__ void mbar_init(uint32_t a, uint32_t c) {
    asm volatile("mbarrier.init.shared.b64 [%0], %1;" :: "r"(a), "r"(c) : "memory");
}
__device__ __forceinline__ void mbar_inval(uint32_t a) {
    asm volatile("mbarrier.inval.shared.b64 [%0];" :: "r"(a) : "memory");
}
__device__ __forceinline__ void mbar_arrive_rank0(uint32_t a) {
    asm volatile("{ .reg .b32 ra; mapa.shared::cluster.u32 ra, %0, 0;"
                 " mbarrier.arrive.shared::cluster.b64 _, [ra]; }" :: "r"(a) : "memory");
}
__device__ __forceinline__ void mbar_wait(uint32_t a, uint32_t parity) {
    asm volatile("{ .reg .pred P;\n"
                 "W%=: mbarrier.try_wait.parity.acquire.cta.shared::cta.b64 P, [%0], %1, 0x989680;\n"
                 "@P bra D%=;\n bra W%=;\nD%=: }"
                 :: "r"(a), "r"(parity) : "memory");
}
__device__ __forceinline__ void fence_async() {
    asm volatile("fence.proxy.async.shared::cta;" ::: "memory");
}
constexpr uint64_t DESC_BASE = (2ull<<61) | (1ull<<46) | (64ull<<32) | (1ull<<16);
__device__ __forceinline__ uint64_t mk_desc(uint32_t a) { return DESC_BASE | ((a >> 4) & 0x3FFF); }
constexpr uint32_t IDESC = (1u<<4) | (1u<<7) | (1u<<10) | ((256/8)<<17) | ((256/16)<<24);

__device__ __forceinline__ void mma_cg2(uint32_t d, uint64_t ad, uint64_t bd, uint32_t en) {
    asm volatile("{ .reg .pred p; setp.ne.u32 p, %5, 0;\n"
                 "tcgen05.mma.cta_group::2.kind::f16 [%0], %1, %2, %3,"
                 " {%4,%4,%4,%4,%4,%4,%4,%4}, p; }"
                 :: "r"(d), "l"(ad), "l"(bd), "r"(IDESC), "r"(0u), "r"(en) : "memory");
}

// ---------------------------------------------------------------- split helpers
__device__ __forceinline__ void split2(float v, __nv_bfloat16& hi, __nv_bfloat16& lo) {
    hi = __float2bfloat16(v);
    lo = __float2bfloat16(v - __bfloat162float(hi));
}
__device__ __forceinline__ uint32_t pack2(__nv_bfloat16 a, __nv_bfloat16 b) {
    __nv_bfloat162 t(a, b);
    return *reinterpret_cast<uint32_t*>(&t);
}

// store one float4 (already in regs) as hi/lo bf16x4 to swizzled smem
__device__ __forceinline__ void store_split4(uint32_t dhi, uint32_t dlo, uint32_t sw, float4 v) {
    __nv_bfloat16 h0,l0,h1,l1,h2,l2,h3,l3;
    split2(v.x,h0,l0); split2(v.y,h1,l1); split2(v.z,h2,l2); split2(v.w,h3,l3);
    asm volatile("st.shared.v2.u32 [%0], {%1,%2};"
                 :: "r"(dhi + sw), "r"(pack2(h0,h1)), "r"(pack2(h2,h3)));
    asm volatile("st.shared.v2.u32 [%0], {%1,%2};"
                 :: "r"(dlo + sw), "r"(pack2(l0,l1)), "r"(pack2(l2,l3)));
}

// bf16 128x64 tile raw copy -> swizzled smem (blocking; used for tiny ext chunks)
__device__ __forceinline__ void copy_tile_bf16(uint32_t dst, const __nv_bfloat16* __restrict__ src,
                                               int ld, int tid) {
    const int r0 = tid >> 3, u = tid & 7;
#pragma unroll
    for (int p = 0; p < 4; p++) {
        int r = r0 + p * 32;
        uint4 v = *reinterpret_cast<const uint4*>(src + (size_t)r * ld + u * 8);
        uint32_t off = (uint32_t)(r * 128 + u * 16);
        uint32_t sw = off ^ ((off >> 3) & 0x70);
        asm volatile("st.shared.v4.u32 [%0], {%1,%2,%3,%4};"
                     :: "r"(dst + sw), "r"(v.x), "r"(v.y), "r"(v.z), "r"(v.w));
    }
}

// ---------------------------------------------------------------- pack kernels
__global__ void split_proj_kernel(const float* __restrict__ Wq,
                                  const float* __restrict__ Wk,
                                  const float* __restrict__ A) {
    size_t t = (size_t)blockIdx.x * 256 + threadIdx.x;
    if (t >= (size_t)NPROJ_PAD * DIN / 4) return;
    int row = (int)(t / (DIN / 4)), col = (int)(t % (DIN / 4)) * 4;
    float4 v = make_float4(0.f, 0.f, 0.f, 0.f);
    if (row < 256)      v = *reinterpret_cast<const float4*>(Wq + (size_t)row * DIN + col);
    else if (row < 512) v = *reinterpret_cast<const float4*>(Wk + (size_t)(row - 256) * DIN + col);
    else if (row < 640) v = *reinterpret_cast<const float4*>(A  + (size_t)(row - 512) * DIN + col);
    *reinterpret_cast<uint2*>(g_Pp + (size_t)row * DIN + col) =
        make_uint2(pack2(__float2bfloat16(v.x), __float2bfloat16(v.y)),
                   pack2(__float2bfloat16(v.z), __float2bfloat16(v.w)));
}

// B2[o,j]: j<128 -> Bm[e,o,r]; j==128 -> b[o]; else 0. hi at j, lo at 192+j.
__global__ void pack_b2_kernel(const float* __restrict__ Bm, const float* __restrict__ b) {
    int idx = blockIdx.x * 256 + threadIdx.x;
    if (idx >= DOUT * GEXT) return;
    int o = idx / GEXT, j = idx - o * GEXT;
    float v = 0.f;
    if (j < E * R) { int e = j >> 4, r = j & 15; v = Bm[((size_t)e * DOUT + o) * R + r]; }
    else if (j == E * R) v = b[o];
    __nv_bfloat16 hi, lo; split2(v, hi, lo);
    g_B2[(size_t)o * GLD + j] = hi;
    g_B2[(size_t)o * GLD + GEXT + j] = lo;
}

// ---------------------------------------------------------------- routing
__global__ void routing_kernel() {
    int warp = (blockIdx.x * blockDim.x + threadIdx.x) >> 5;
    int lane = threadIdx.x & 31;
    if (warp >= MTOK) return;
    const float* Pt = g_P + (size_t)warp * NPROJ_PAD;
    float s[E];
#pragma unroll
    for (int e = 0; e < E; e++) {
        float p = Pt[e * DK + lane] * Pt[E * DK + e * DK + lane];
#pragma unroll
        for (int o = 16; o > 0; o >>= 1) p += __shfl_xor_sync(0xffffffffu, p, o);
        s[e] = p * 0.17677669529663687f;
    }
    float m = s[0];
#pragma unroll
    for (int e = 1; e < E; e++) m = fmaxf(m, s[e]);
    float Z = 0.f;
#pragma unroll
    for (int e = 0; e < E; e++) { s[e] = __expf(s[e] - m); Z += s[e]; }
    float inv = 1.f / Z;

    __nv_bfloat16* Gt = g_Gx + (size_t)warp * GLD;
#pragma unroll
    for (int j = lane; j < GEXT; j += 32) {
        float g = 0.f;
        if (j < E * R)       g = s[j >> 4] * inv * Pt[2 * E * DK + j];
        else if (j == E * R) g = 1.0f;
        __nv_bfloat16 hi, lo; split2(g, hi, lo);
        Gt[j] = hi;
        Gt[GEXT + j] = lo;
    }
}

// ---------------------------------------------------------------- proj GEMM
// Fused fp32->bf16(hi) convert of A with ONE-CHUNK-AHEAD register prefetch;
// B copied from pre-split g_Pp. NST=2.
__global__ void __cluster_dims__(2, 1, 1) __launch_bounds__(256, 1)
gemm_proj_kernel(const float* __restrict__ xg) {
#if defined(__CUDA_ARCH_FEAT_SM103_ALL)
    constexpr int NST = 2, NCH = DIN / 64, STAGE = 32768;   // A 16KB + B 16KB
    constexpr int SLAST = (NCH - 1) & (NST - 1);            // 1
    constexpr uint32_t FINPAR = 1;                          // 32nd commit on slot1

    extern __shared__ char smem[];
    const uint32_t sbase = smem_u32(smem);
    const int tid = threadIdx.x, wid = tid >> 5, lane = tid & 31;
    const uint32_t rank = ctarank();
    const int n_tile = blockIdx.x >> 1, m_tile = blockIdx.y;
    const uint32_t FULL0 = sbase + 8, MMAB0 = sbase + 40;

    if (tid == 0)
        for (int s = 0; s < NST; s++) { mbar_init(FULL0 + s * 8, 2); mbar_init(MMAB0 + s * 8, 1); }
    if (wid == 0)
        asm volatile("tcgen05.alloc.cta_group::2.sync.aligned.shared::cta.b32 [%0], %1;"
                     :: "r"(sbase), "r"(512) : "memory");
    __syncthreads();
    uint32_t tmem;
    asm volatile("ld.shared.b32 %0, [%1];" : "=r"(tmem) : "r"(sbase));
    cluster_sync();

    const float* Arow = xg + (size_t)(m_tile * 256 + rank * 128) * DIN;
    const __nv_bfloat16* Brow = g_Pp + (size_t)(n_tile * 256 + rank * 128) * DIN;

    const int r0 = tid >> 4, c4 = (tid & 15) * 4;     // A mapping
    const int r0b = tid >> 3, ub = tid & 7;           // B mapping
    float4 ra[8];
    uint4  rb[4];

    auto prefetch = [&](int chunk) {
        const int kb = chunk * 64;
#pragma unroll
        for (int p = 0; p < 8; p++)
            ra[p] = *reinterpret_cast<const float4*>(Arow + (size_t)(r0 + p * 16) * DIN + kb + c4);
#pragma unroll
        for (int p = 0; p < 4; p++)
            rb[p] = *reinterpret_cast<const uint4*>(Brow + (size_t)(r0b + p * 32) * DIN + kb + ub * 8);
    };
    auto convert_store = [&](uint32_t st) {
#pragma unroll
        for (int p = 0; p < 8; p++) {
            uint32_t off = (uint32_t)((r0 + p * 16) * 128 + (tid & 15) * 8);
            uint32_t sw = off ^ ((off >> 3) & 0x70);
            asm volatile("st.shared.v2.u32 [%0], {%1,%2};"
                         :: "r"(st + sw),
                            "r"(pack2(__float2bfloat16(ra[p].x), __float2bfloat16(ra[p].y))),
                            "r"(pack2(__float2bfloat16(ra[p].z), __float2bfloat16(ra[p].w))));
        }
#pragma unroll
        for (int p = 0; p < 4; p++) {
            uint32_t off = (uint32_t)((r0b + p * 32) * 128 + ub * 16);
            uint32_t sw = off ^ ((off >> 3) & 0x70);
            asm volatile("st.shared.v4.u32 [%0], {%1,%2,%3,%4};"
                         :: "r"(st + 16384 + sw), "r"(rb[p].x), "r"(rb[p].y), "r"(rb[p].z), "r"(rb[p].w));
        }
    };

    uint32_t fph[NST] = {}, mph[NST] = {};
    prefetch(0);
    for (int i = 0; i < NCH; i++) {
        const int s = i & (NST - 1);
        if (i >= NST) { mbar_wait(MMAB0 + s * 8, mph[s]); mph[s] ^= 1; }
        const uint32_t st = sbase + 1024 + s * STAGE;
        convert_store(st);
        if (i + 1 < NCH) prefetch(i + 1);
        fence_async();
        __syncthreads();
        if (tid == 0) mbar_arrive_rank0(FULL0 + s * 8);
        if (rank == 0 && tid == 0) {
            mbar_wait(FULL0 + s * 8, fph[s]); fph[s] ^= 1;
            uint64_t ad = mk_desc(st), bd = mk_desc(st + 16384);
#pragma unroll
            for (int kk = 0; kk < 4; kk++)
                mma_cg2(tmem, ad + kk * 2, bd + kk * 2, (i > 0) || (kk > 0));
            asm volatile("tcgen05.commit.cta_group::2.mbarrier::arrive::one.shared::cluster.multicast::cluster.b64 [%0], %1;"
                         :: "r"(MMAB0 + s * 8), "h"((uint16_t)3) : "memory");
        }
    }
    mbar_wait(MMAB0 + SLAST * 8, FINPAR);
    asm volatile("tcgen05.fence::after_thread_sync;" ::: "memory");

    {
        const int gm = m_tile * 256 + (int)rank * 128 + (wid & 3) * 32 + lane;
        float* crow = g_P + (size_t)gm * NPROJ_PAD + n_tile * 256 + (wid >> 2) * 128;
        const uint32_t cb0 = tmem + (uint32_t)((wid >> 2) * 128);
#pragma unroll
        for (int cb = 0; cb < 128; cb += 32) {
            uint32_t d[32];
            asm volatile("tcgen05.ld.sync.aligned.32x32b.x32.b32 "
                "{%0,%1,%2,%3,%4,%5,%6,%7,%8,%9,%10,%11,%12,%13,%14,%15,"
                "%16,%17,%18,%19,%20,%21,%22,%23,%24,%25,%26,%27,%28,%29,%30,%31}, [%32];"
                : "=r"(d[0]),"=r"(d[1]),"=r"(d[2]),"=r"(d[3]),"=r"(d[4]),"=r"(d[5]),"=r"(d[6]),"=r"(d[7]),
                  "=r"(d[8]),"=r"(d[9]),"=r"(d[10]),"=r"(d[11]),"=r"(d[12]),"=r"(d[13]),"=r"(d[14]),"=r"(d[15]),
                  "=r"(d[16]),"=r"(d[17]),"=r"(d[18]),"=r"(d[19]),"=r"(d[20]),"=r"(d[21]),"=r"(d[22]),"=r"(d[23]),
                  "=r"(d[24]),"=r"(d[25]),"=r"(d[26]),"=r"(d[27]),"=r"(d[28]),"=r"(d[29]),"=r"(d[30]),"=r"(d[31])
                : "r"(cb0 + cb));
            asm volatile("tcgen05.wait::ld.sync.aligned;" ::: "memory");
#pragma unroll
            for (int c = 0; c < 32; c += 4)
                *reinterpret_cast<float4*>(crow + cb + c) =
                    make_float4(__uint_as_float(d[c]), __uint_as_float(d[c+1]),
                                __uint_as_float(d[c+2]), __uint_as_float(d[c+3]));
        }
    }
    __syncthreads();
    if (tid == 0) {
        for (int s = 0; s < NST; s++) { mbar_inval(FULL0 + s * 8); mbar_inval(MMAB0 + s * 8); }
    }
    __syncthreads();
    if (wid == 0) {
        asm volatile("tcgen05.relinquish_alloc_permit.cta_group::2.sync.aligned;");
        asm volatile("tcgen05.dealloc.cta_group::2.sync.aligned.b32 %0, %1;" :: "r"(tmem), "r"(512));
    }
    cluster_sync();
#endif
}

// ---------------------------------------------------------------- main GEMM
// Fused fp32->(hi,lo) convert with one-chunk-ahead register prefetch.
// 3-product dedup, TN=512/pair, NST=2.
__global__ void __cluster_dims__(2, 1, 1) __launch_bounds__(256, 1)
gemm_main_kernel(const float* __restrict__ xg, const float* __restrict__ Wg,
                 float* __restrict__ Cg) {
#if defined(__CUDA_ARCH_FEAT_SM103_ALL)
    constexpr int NST = 2;
    constexpr int NCH = DIN / 64 + GEXT / 64;       // 64 + 3 = 67
    constexpr int STAGE = 98304;                    // A 32KB + B 64KB
    constexpr int A_HI = 0, A_LO = 16384, B_HI = 32768, B_LO = 65536;
    constexpr int SLAST = (NCH - 1) & (NST - 1);    // 0
    constexpr uint32_t FINPAR = 1;                  // 34th commit on slot0

    extern __shared__ char smem[];
    const uint32_t sbase = smem_u32(smem);
    const int tid = threadIdx.x, wid = tid >> 5, lane = tid & 31;
    const uint32_t rank = ctarank();
    const int n_tile = blockIdx.x >> 1, m_tile = blockIdx.y;
    const uint32_t FULL0 = sbase + 8, MMAB0 = sbase + 40;

    if (tid == 0)
        for (int s = 0; s < NST; s++) { mbar_init(FULL0 + s * 8, 2); mbar_init(MMAB0 + s * 8, 1); }
    if (wid == 0)
        asm volatile("tcgen05.alloc.cta_group::2.sync.aligned.shared::cta.b32 [%0], %1;"
                     :: "r"(sbase), "r"(512) : "memory");
    __syncthreads();
    uint32_t tmem;
    asm volatile("ld.shared.b32 %0, [%1];" : "=r"(tmem) : "r"(sbase));
    cluster_sync();

    const int arow0 = m_tile * 256 + (int)rank * 128;
    const int brow0 = n_tile * 512 + (int)rank * 128;
    const float* Arow = xg + (size_t)arow0 * DIN;
    const float* Brow = Wg + (size_t)brow0 * DIN;
    const __nv_bfloat16* Aext = g_Gx + (size_t)arow0 * GLD;
    const __nv_bfloat16* Bext = g_B2 + (size_t)brow0 * GLD;

    const int r0 = tid >> 4, c4 = (tid & 15) * 4;
    float4 ra[8], rb0[8], rb1[8];

    auto prefetch = [&](int chunk) {
        const int kb = chunk * 64;
#pragma unroll
        for (int p = 0; p < 8; p++) {
            const size_t ro = (size_t)(r0 + p * 16) * DIN + kb + c4;
            ra[p]  = *reinterpret_cast<const float4*>(Arow + ro);
            rb0[p] = *reinterpret_cast<const float4*>(Brow + ro);
            rb1[p] = *reinterpret_cast<const float4*>(Brow + (size_t)256 * DIN + ro);
        }
    };
    auto convert_store = [&](uint32_t st) {
#pragma unroll
        for (int p = 0; p < 8; p++) {
            uint32_t off = (uint32_t)((r0 + p * 16) * 128 + (tid & 15) * 8);
            uint32_t sw = off ^ ((off >> 3) & 0x70);
            store_split4(st + A_HI, st + A_LO, sw, ra[p]);
            store_split4(st + B_HI, st + B_LO, sw, rb0[p]);
            store_split4(st + B_HI + 16384, st + B_LO + 16384, sw, rb1[p]);
        }
    };

    uint32_t fph[NST] = {}, mph[NST] = {};
    prefetch(0);
    for (int i = 0; i < NCH; i++) {
        const int s = i & (NST - 1);
        if (i >= NST) { mbar_wait(MMAB0 + s * 8, mph[s]); mph[s] ^= 1; }
        const uint32_t st = sbase + 1024 + s * STAGE;
        if (i < 64) {
            convert_store(st);
            if (i + 1 < 64) prefetch(i + 1);
        } else {
            const int cb = (i - 64) * 64;
            copy_tile_bf16(st + A_HI, Aext + cb, GLD, tid);
            copy_tile_bf16(st + A_LO, Aext + GEXT + cb, GLD, tid);
            copy_tile_bf16(st + B_HI, Bext + cb, GLD, tid);
            copy_tile_bf16(st + B_LO, Bext + GEXT + cb, GLD, tid);
            copy_tile_bf16(st + B_HI + 16384, Bext + (size_t)256 * GLD + cb, GLD, tid);
            copy_tile_bf16(st + B_LO + 16384, Bext + (size_t)256 * GLD + GEXT + cb, GLD, tid);
        }
        fence_async();
        __syncthreads();
        if (tid == 0) mbar_arrive_rank0(FULL0 + s * 8);
        if (rank == 0 && tid == 0) {
            mbar_wait(FULL0 + s * 8, fph[s]); fph[s] ^= 1;
            uint64_t ahi = mk_desc(st + A_HI), alo = mk_desc(st + A_LO);
#pragma unroll
            for (int h = 0; h < 2; h++) {
                uint64_t bhi = mk_desc(st + B_HI + h * 16384);
                uint64_t blo = mk_desc(st + B_LO + h * 16384);
                uint32_t dh = tmem + h * 256;
#pragma unroll
                for (int kk = 0; kk < 4; kk++) {
                    uint32_t en = ((i > 0) || (kk > 0)) ? 1u : 0u;   // first MMA per half inits acc
                    mma_cg2(dh, ahi + kk * 2, bhi + kk * 2, en);
                    mma_cg2(dh, alo + kk * 2, bhi + kk * 2, 1u);
                    mma_cg2(dh, ahi + kk * 2, blo + kk * 2, 1u);
                }
            }
            asm volatile("tcgen05.commit.cta_group::2.mbarrier::arrive::one.shared::cluster.multicast::cluster.b64 [%0], %1;"
                         :: "r"(MMAB0 + s * 8), "h"((uint16_t)3) : "memory");
        }
    }
    mbar_wait(MMAB0 + SLAST * 8, FINPAR);
    asm volatile("tcgen05.fence::after_thread_sync;" ::: "memory");

    // epilogue
    {
        const int gm = arow0 + (wid & 3) * 32 + lane;
        float* crow = Cg + (size_t)gm * DOUT + n_tile * 512 + (wid >> 2) * 256;
        const uint32_t cb0 = tmem + (uint32_t)((wid >> 2) * 256);
#pragma unroll
        for (int cb = 0; cb < 256; cb += 32) {
            uint32_t d[32];
            asm volatile("tcgen05.ld.sync.aligned.32x32b.x32.b32 "
                "{%0,%1,%2,%3,%4,%5,%6,%7,%8,%9,%10,%11,%12,%13,%14,%15,"
                "%16,%17,%18,%19,%20,%21,%22,%23,%24,%25,%26,%27,%28,%29,%30,%31}, [%32];"
                : "=r"(d[0]),"=r"(d[1]),"=r"(d[2]),"=r"(d[3]),"=r"(d[4]),"=r"(d[5]),"=r"(d[6]),"=r"(d[7]),
                  "=r"(d[8]),"=r"(d[9]),"=r"(d[10]),"=r"(d[11]),"=r"(d[12]),"=r"(d[13]),"=r"(d[14]),"=r"(d[15]),
                  "=r"(d[16]),"=r"(d[17]),"=r"(d[18]),"=r"(d[19]),"=r"(d[20]),"=r"(d[21]),"=r"(d[22]),"=r"(d[23]),
                  "=r"(d[24]),"=r"(d[25]),"=r"(d[26]),"=r"(d[27]),"=r"(d[28]),"=r"(d[29]),"=r"(d[30]),"=r"(d[31])
                : "r"(cb0 + cb));
            asm volatile("tcgen05.wait::ld.sync.aligned;" ::: "memory");
#pragma unroll
            for (int c = 0; c < 32; c += 4)
                *reinterpret_cast<float4*>(crow + cb + c) =
                    make_float4(__uint_as_float(d[c]), __uint_as_float(d[c+1]),
                                __uint_as_float(d[c+2]), __uint_as_float(d[c+3]));
        }
    }
    __syncthreads();
    if (tid == 0) {
        for (int s = 0; s < NST; s++) { mbar_inval(FULL0 + s * 8); mbar_inval(MMAB0 + s * 8); }
    }
    __syncthreads();
    if (wid == 0) {
        asm volatile("tcgen05.relinquish_alloc_permit.cta_group::2.sync.aligned;");
        asm volatile("tcgen05.dealloc.cta_group::2.sync.aligned.b32 %0, %1;" :: "r"(tmem), "r"(512));
    }
    cluster_sync();
#endif
}

// ---------------------------------------------------------------- launch
// Inputs (metadata order): x, W, b, Wq, Wk, A, Bm
extern "C" void kernel_launch(void* const* d_in, const int* in_sizes, int n_in,
                              void* d_out, int out_size) {
    const float* x  = (const float*)d_in[0];
    const float* W  = (const float*)d_in[1];
    const float* b  = (const float*)d_in[2];
    const float* Wq = (const float*)d_in[3];
    const float* Wk = (const float*)d_in[4];
    const float* A  = (const float*)d_in[5];
    const float* Bm = (const float*)d_in[6];
    float* out = (float*)d_out;

    constexpr int SMEM0 = 1024 + 2 * 32768;    // 66560
    constexpr int SMEM1 = 1024 + 2 * 98304;    // 197632
    cudaFuncSetAttribute(gemm_proj_kernel, cudaFuncAttributeMaxDynamicSharedMemorySize, SMEM0);
    cudaFuncSetAttribute(gemm_main_kernel, cudaFuncAttributeMaxDynamicSharedMemorySize, SMEM1);

    split_proj_kernel<<<(int)(((size_t)NPROJ_PAD * DIN / 4 + 255) / 256), 256>>>(Wq, Wk, A);
    pack_b2_kernel   <<<(DOUT * GEXT + 255) / 256, 256>>>(Bm, b);

    // projections P = x_hi @ [Wq;Wk;A]_hi^T  (fused convert, register-prefetched)
    gemm_proj_kernel<<<dim3(2 * (NPROJ_PAD / 256), MTOK / 256), 256, SMEM0>>>(x);

    // routing -> G ext panels (hi|lo) in g_Gx
    routing_kernel<<<(MTOK * 32) / 256, 256>>>();

    // out = x @ W^T + G @ B2^T (+bias): fused-convert dedup 3-product GEMM
    gemm_main_kernel<<<dim3(2 * (DOUT / 512), MTOK / 256), 256, SMEM1>>>(x, W, out);
}

// round 13
// speedup vs baseline: 1.3506x; 1.2266x over previous
#include <cuda_runtime.h>
#include <cuda_bf16.h>
#include <cstdint>

// ---------------------------------------------------------------- constants
constexpr int MTOK = 8192, DIN = 4096, DOUT = 4096;
constexpr int E = 8, DK = 32, R = 16;
constexpr int NPROJ = 640, NPROJ_PAD = 768;
constexpr int GEXT  = 192;                 // ext cols: 128 lora + 1 bias + 63 pad (hi only)
constexpr int EXT0  = 2 * DIN;             // 8192
constexpr int KP2   = 2 * DIN + GEXT;      // 8384: [hi | lo | ext_hi]

// ---------------------------------------------------------------- scratch
__device__ __align__(1024) __nv_bfloat16 g_Xp[(size_t)MTOK * KP2];
__device__ __align__(1024) __nv_bfloat16 g_Wp[(size_t)DOUT * KP2];
__device__ __align__(1024) __nv_bfloat16 g_Pp[(size_t)NPROJ_PAD * DIN];
__device__ __align__(1024) float         g_P [(size_t)MTOK * NPROJ_PAD];

// ---------------------------------------------------------------- ptx utils
__device__ __forceinline__ uint32_t smem_u32(const void* p) {
    uint32_t a;
    asm("{ .reg .u64 t; cvta.to.shared.u64 t, %1; cvt.u32.u64 %0, t; }" : "=r"(a) : "l"(p));
    return a;
}
__device__ __forceinline__ uint32_t ctarank() {
    uint32_t r; asm("mov.u32 %0, %%cluster_ctarank;" : "=r"(r)); return r;
}
__device__ __forceinline__ void cluster_sync() {
    asm volatile("barrier.cluster.arrive.aligned;" ::: "memory");
    asm volatile("barrier.cluster.wait.aligned;" ::: "memory");
}
__device__ __forceinline__ void mbar_init(uint32_t a, uint32_t c) {
    asm volatile("mbarrier.init.shared.b64 [%0], %1;" :: "r"(a), "r"(c) : "memory");
}
__device__ __forceinline__ void mbar_inval(uint32_t a) {
    asm volatile("mbarrier.inval.shared.b64 [%0];" :: "r"(a) : "memory");
}
__device__ __forceinline__ void mbar_arrive_rank0(uint32_t a) {
    asm volatile("{ .reg .b32 ra; mapa.shared::cluster.u32 ra, %0, 0;"
                 " mbarrier.arrive.shared::cluster.b64 _, [ra]; }" :: "r"(a) : "memory");
}
__device__ __forceinline__ void mbar_wait(uint32_t a, uint32_t parity) {
    asm volatile("{ .reg .pred P;\n"
                 "W%=: mbarrier.try_wait.parity.acquire.cta.shared::cta.b64 P, [%0], %1, 0x989680;\n"
                 "@P bra D%=;\n bra W%=;\nD%=: }"
                 :: "r"(a), "r"(parity) : "memory");
}
__device__ __forceinline__ void cpa16(uint32_t s, const void* g) {
    asm volatile("cp.async.cg.shared.global [%0], [%1], 16;" :: "r"(s), "l"(g));
}
__device__ __forceinline__ void cp_commit() { asm volatile("cp.async.commit_group;"); }
template <int N> __device__ __forceinline__ void cp_wait() {
    asm volatile("cp.async.wait_group %0;" :: "n"(N));
}
__device__ __forceinline__ void fence_async() {
    asm volatile("fence.proxy.async.shared::cta;" ::: "memory");
}
constexpr uint64_t DESC_BASE = (2ull<<61) | (1ull<<46) | (64ull<<32) | (1ull<<16);
__device__ __forceinline__ uint64_t mk_desc(uint32_t a) { return DESC_BASE | ((a >> 4) & 0x3FFF); }
constexpr uint32_t IDESC = (1u<<4) | (1u<<7) | (1u<<10) | ((256/8)<<17) | ((256/16)<<24);

__device__ __forceinline__ void mma_cg2(uint32_t d, uint64_t ad, uint64_t bd, uint32_t en) {
    asm volatile("{ .reg .pred p; setp.ne.u32 p, %5, 0;\n"
                 "tcgen05.mma.cta_group::2.kind::f16 [%0], %1, %2, %3,"
                 " {%4,%4,%4,%4,%4,%4,%4,%4}, p; }"
                 :: "r"(d), "l"(ad), "l"(bd), "r"(IDESC), "r"(0u), "r"(en) : "memory");
}

// ---------------------------------------------------------------- split helpers
__device__ __forceinline__ void split2(float v, __nv_bfloat16& hi, __nv_bfloat16& lo) {
    hi = __float2bfloat16(v);
    lo = __float2bfloat16(v - __bfloat162float(hi));
}
__device__ __forceinline__ uint32_t pack2(__nv_bfloat16 a, __nv_bfloat16 b) {
    __nv_bfloat162 t(a, b);
    return *reinterpret_cast<uint32_t*>(&t);
}

// ---------------------------------------------------------------- merged split x+W
// One row per block; each thread: 4 independent float4 loads (MLP=4), uint2 stores.
__global__ void __launch_bounds__(256) split_xw_kernel(const float* __restrict__ x,
                                                       const float* __restrict__ W) {
    const int row = blockIdx.x;
    const float* src;
    __nv_bfloat16* dst;
    if (row < MTOK) { src = x + (size_t)row * DIN; dst = g_Xp + (size_t)row * KP2; }
    else { src = W + (size_t)(row - MTOK) * DIN; dst = g_Wp + (size_t)(row - MTOK) * KP2; }
    const int t = threadIdx.x;
    float4 v[4];
#pragma unroll
    for (int j = 0; j < 4; j++)
        v[j] = *reinterpret_cast<const float4*>(src + (t + j * 256) * 4);
#pragma unroll
    for (int j = 0; j < 4; j++) {
        int col = (t + j * 256) * 4;
        __nv_bfloat16 h0,l0,h1,l1,h2,l2,h3,l3;
        split2(v[j].x,h0,l0); split2(v[j].y,h1,l1); split2(v[j].z,h2,l2); split2(v[j].w,h3,l3);
        *reinterpret_cast<uint2*>(dst + col)       = make_uint2(pack2(h0,h1), pack2(h2,h3));
        *reinterpret_cast<uint2*>(dst + DIN + col) = make_uint2(pack2(l0,l1), pack2(l2,l3));
    }
}

// ---------------------------------------------------------------- pack kernels
__global__ void split_proj_kernel(const float* __restrict__ Wq,
                                  const float* __restrict__ Wk,
                                  const float* __restrict__ A) {
    size_t t = (size_t)blockIdx.x * 256 + threadIdx.x;
    if (t >= (size_t)NPROJ_PAD * DIN / 4) return;
    int row = (int)(t / (DIN / 4)), col = (int)(t % (DIN / 4)) * 4;
    float4 v = make_float4(0.f, 0.f, 0.f, 0.f);
    if (row < 256)      v = *reinterpret_cast<const float4*>(Wq + (size_t)row * DIN + col);
    else if (row < 512) v = *reinterpret_cast<const float4*>(Wk + (size_t)(row - 256) * DIN + col);
    else if (row < 640) v = *reinterpret_cast<const float4*>(A  + (size_t)(row - 512) * DIN + col);
    *reinterpret_cast<uint2*>(g_Pp + (size_t)row * DIN + col) =
        make_uint2(pack2(__float2bfloat16(v.x), __float2bfloat16(v.y)),
                   pack2(__float2bfloat16(v.z), __float2bfloat16(v.w)));
}

// B2 ext (hi only): g_Wp cols [8192, 8384). j<128 -> Bm[e,o,r]; j==128 -> b[o]; else 0.
__global__ void pack_b2_kernel(const float* __restrict__ Bm, const float* __restrict__ b) {
    int idx = blockIdx.x * 256 + threadIdx.x;
    if (idx >= DOUT * GEXT) return;
    int o = idx / GEXT, j = idx - o * GEXT;
    float v = 0.f;
    if (j < E * R) { int e = j >> 4, r = j & 15; v = Bm[((size_t)e * DOUT + o) * R + r]; }
    else if (j == E * R) v = b[o];
    g_Wp[(size_t)o * KP2 + EXT0 + j] = __float2bfloat16(v);
}

// ---------------------------------------------------------------- routing (ext hi only)
__global__ void routing_kernel() {
    int warp = (blockIdx.x * blockDim.x + threadIdx.x) >> 5;
    int lane = threadIdx.x & 31;
    if (warp >= MTOK) return;
    const float* Pt = g_P + (size_t)warp * NPROJ_PAD;
    float s[E];
#pragma unroll
    for (int e = 0; e < E; e++) {
        float p = Pt[e * DK + lane] * Pt[E * DK + e * DK + lane];
#pragma unroll
        for (int o = 16; o > 0; o >>= 1) p += __shfl_xor_sync(0xffffffffu, p, o);
        s[e] = p * 0.17677669529663687f;
    }
    float m = s[0];
#pragma unroll
    for (int e = 1; e < E; e++) m = fmaxf(m, s[e]);
    float Z = 0.f;
#pragma unroll
    for (int e = 0; e < E; e++) { s[e] = __expf(s[e] - m); Z += s[e]; }
    float inv = 1.f / Z;

    __nv_bfloat16* Gt = g_Xp + (size_t)warp * KP2 + EXT0;
#pragma unroll
    for (int j = lane; j < GEXT; j += 32) {
        float g = 0.f;
        if (j < E * R)       g = s[j >> 4] * inv * Pt[2 * E * DK + j];
        else if (j == E * R) g = 1.0f;
        Gt[j] = __float2bfloat16(g);
    }
}

// ---------------------------------------------------------------- proj GEMM (R9-proven)
__global__ void __cluster_dims__(2, 1, 1) __launch_bounds__(256, 1)
gemm_proj_kernel() {
#if defined(__CUDA_ARCH_FEAT_SM103_ALL)
    constexpr int NST = 4, NCH = DIN / 64, STAGE = 32768;
    constexpr int SLAST = (NCH - 1) & (NST - 1);
    constexpr uint32_t FINPAR = (((NCH - 1 - SLAST) / NST + 1) - 1) & 1;

    extern __shared__ char smem[];
    const uint32_t sbase = smem_u32(smem);
    const int tid = threadIdx.x, wid = tid >> 5, lane = tid & 31;
    const uint32_t rank = ctarank();
    const int n_tile = blockIdx.x >> 1, m_tile = blockIdx.y;
    const uint32_t FULL0 = sbase + 8, MMAB0 = sbase + 40;

    if (tid == 0)
        for (int s = 0; s < NST; s++) { mbar_init(FULL0 + s * 8, 2); mbar_init(MMAB0 + s * 8, 1); }
    if (wid == 0)
        asm volatile("tcgen05.alloc.cta_group::2.sync.aligned.shared::cta.b32 [%0], %1;"
                     :: "r"(sbase), "r"(512) : "memory");
    __syncthreads();
    uint32_t tmem;
    asm volatile("ld.shared.b32 %0, [%1];" : "=r"(tmem) : "r"(sbase));
    cluster_sync();

    const __nv_bfloat16* Arow = g_Xp + (size_t)(m_tile * 256 + rank * 128) * KP2;
    const __nv_bfloat16* Brow = g_Pp + (size_t)(n_tile * 256 + rank * 128) * DIN;

    auto fill = [&](int chunk) {
        const int kb = chunk * 64;
        const uint32_t st = sbase + 1024 + (chunk & (NST - 1)) * STAGE;
#pragma unroll
        for (int p = 0; p < 4; p++) {
            int q = p * 256 + tid, r = q >> 3, c = q & 7;
            uint32_t off = (uint32_t)(r * 128 + c * 16);
            uint32_t sw = off ^ ((off >> 3) & 0x70);
            cpa16(st + sw, Arow + (size_t)r * KP2 + kb + c * 8);
            cpa16(st + 16384 + sw, Brow + (size_t)r * DIN + kb + c * 8);
        }
        cp_commit();
    };

    uint32_t fph[NST] = {}, mph[NST] = {};
    fill(0); fill(1); fill(2);
    for (int i = 0; i < NCH; i++) {
        const int s = i & (NST - 1), rem = NCH - 1 - i;
        if (rem >= 2) cp_wait<2>(); else if (rem == 1) cp_wait<1>(); else cp_wait<0>();
        __syncthreads();
        if (tid == 0) { fence_async(); mbar_arrive_rank0(FULL0 + s * 8); }
        if (rank == 0 && tid == 0) {
            mbar_wait(FULL0 + s * 8, fph[s]); fph[s] ^= 1;
            const uint32_t st = sbase + 1024 + s * STAGE;
            uint64_t ad = mk_desc(st), bd = mk_desc(st + 16384);
#pragma unroll
            for (int kk = 0; kk < 4; kk++)
                mma_cg2(tmem, ad + kk * 2, bd + kk * 2, (i > 0) || (kk > 0));
            asm volatile("tcgen05.commit.cta_group::2.mbarrier::arrive::one.shared::cluster.multicast::cluster.b64 [%0], %1;"
                         :: "r"(MMAB0 + s * 8), "h"((uint16_t)3) : "memory");
        }
        const int j = i + NST - 1;
        if (j < NCH) {
            const int s2 = j & (NST - 1);
            if (j >= NST) { mbar_wait(MMAB0 + s2 * 8, mph[s2]); mph[s2] ^= 1; }
            fill(j);
        }
    }
    mbar_wait(MMAB0 + SLAST * 8, FINPAR);
    asm volatile("tcgen05.fence::after_thread_sync;" ::: "memory");

    {
        const int gm = m_tile * 256 + (int)rank * 128 + (wid & 3) * 32 + lane;
        float* crow = g_P + (size_t)gm * NPROJ_PAD + n_tile * 256 + (wid >> 2) * 128;
        const uint32_t cb0 = tmem + (uint32_t)((wid >> 2) * 128);
#pragma unroll
        for (int cb = 0; cb < 128; cb += 32) {
            uint32_t d[32];
            asm volatile("tcgen05.ld.sync.aligned.32x32b.x32.b32 "
                "{%0,%1,%2,%3,%4,%5,%6,%7,%8,%9,%10,%11,%12,%13,%14,%15,"
                "%16,%17,%18,%19,%20,%21,%22,%23,%24,%25,%26,%27,%28,%29,%30,%31}, [%32];"
                : "=r"(d[0]),"=r"(d[1]),"=r"(d[2]),"=r"(d[3]),"=r"(d[4]),"=r"(d[5]),"=r"(d[6]),"=r"(d[7]),
                  "=r"(d[8]),"=r"(d[9]),"=r"(d[10]),"=r"(d[11]),"=r"(d[12]),"=r"(d[13]),"=r"(d[14]),"=r"(d[15]),
                  "=r"(d[16]),"=r"(d[17]),"=r"(d[18]),"=r"(d[19]),"=r"(d[20]),"=r"(d[21]),"=r"(d[22]),"=r"(d[23]),
                  "=r"(d[24]),"=r"(d[25]),"=r"(d[26]),"=r"(d[27]),"=r"(d[28]),"=r"(d[29]),"=r"(d[30]),"=r"(d[31])
                : "r"(cb0 + cb));
            asm volatile("tcgen05.wait::ld.sync.aligned;" ::: "memory");
#pragma unroll
            for (int c = 0; c < 32; c += 4)
                *reinterpret_cast<float4*>(crow + cb + c) =
                    make_float4(__uint_as_float(d[c]), __uint_as_float(d[c+1]),
                                __uint_as_float(d[c+2]), __uint_as_float(d[c+3]));
        }
    }
    __syncthreads();
    if (tid == 0) {
        for (int s = 0; s < NST; s++) { mbar_inval(FULL0 + s * 8); mbar_inval(MMAB0 + s * 8); }
    }
    __syncthreads();
    if (wid == 0) {
        asm volatile("tcgen05.relinquish_alloc_permit.cta_group::2.sync.aligned;");
        asm volatile("tcgen05.dealloc.cta_group::2.sync.aligned.b32 %0, %1;" :: "r"(tmem), "r"(512));
    }
    cluster_sync();
#endif
}

// ---------------------------------------------------------------- main GEMM (R9 + hi-only ext)
__global__ void __cluster_dims__(2, 1, 1) __launch_bounds__(256, 1)
gemm_main_kernel(float* __restrict__ Cg) {
#if defined(__CUDA_ARCH_FEAT_SM103_ALL)
    constexpr int NST = 2;
    constexpr int NCH = DIN / 64 + GEXT / 64;       // 64 + 3 = 67
    constexpr int STAGE = 98304;                    // A 32KB + B 64KB
    constexpr int A_HI = 0, A_LO = 16384, B_HI = 32768, B_LO = 65536;
    constexpr int SLAST = (NCH - 1) & (NST - 1);    // 0
    constexpr uint32_t FINPAR = (((NCH - 1 - SLAST) / NST + 1) - 1) & 1;  // 1

    extern __shared__ char smem[];
    const uint32_t sbase = smem_u32(smem);
    const int tid = threadIdx.x, wid = tid >> 5, lane = tid & 31;
    const uint32_t rank = ctarank();
    const int n_tile = blockIdx.x >> 1, m_tile = blockIdx.y;
    const uint32_t FULL0 = sbase + 8, MMAB0 = sbase + 40;

    if (tid == 0)
        for (int s = 0; s < NST; s++) { mbar_init(FULL0 + s * 8, 2); mbar_init(MMAB0 + s * 8, 1); }
    if (wid == 0)
        asm volatile("tcgen05.alloc.cta_group::2.sync.aligned.shared::cta.b32 [%0], %1;"
                     :: "r"(sbase), "r"(512) : "memory");
    __syncthreads();
    uint32_t tmem;
    asm volatile("ld.shared.b32 %0, [%1];" : "=r"(tmem) : "r"(sbase));
    cluster_sync();

    const int arow0 = m_tile * 256 + (int)rank * 128;
    const int brow0 = n_tile * 512 + (int)rank * 128;
    const __nv_bfloat16* Arow = g_Xp + (size_t)arow0 * KP2;
    const __nv_bfloat16* Brow = g_Wp + (size_t)brow0 * KP2;

    auto load_tile = [&](uint32_t sdst, const __nv_bfloat16* gsrc) {
#pragma unroll
        for (int p = 0; p < 4; p++) {
            int q = p * 256 + tid, r = q >> 3, c = q & 7;
            uint32_t off = (uint32_t)(r * 128 + c * 16);
            uint32_t sw = off ^ ((off >> 3) & 0x70);
            cpa16(sdst + sw, gsrc + (size_t)r * KP2 + c * 8);
        }
    };

    auto fill = [&](int chunk) {
        const uint32_t st = sbase + 1024 + (chunk & (NST - 1)) * STAGE;
        if (chunk < 64) {
            const int kb = chunk * 64;
            load_tile(st + A_HI, Arow + kb);
            load_tile(st + A_LO, Arow + kb + DIN);
#pragma unroll
            for (int h = 0; h < 2; h++) {
                const __nv_bfloat16* Bh = Brow + (size_t)(h * 256) * KP2;
                load_tile(st + B_HI + h * 16384, Bh + kb);
                load_tile(st + B_LO + h * 16384, Bh + kb + DIN);
            }
        } else {
            const int kb = EXT0 + (chunk - 64) * 64;
            load_tile(st + A_HI, Arow + kb);
#pragma unroll
            for (int h = 0; h < 2; h++)
                load_tile(st + B_HI + h * 16384, Brow + (size_t)(h * 256) * KP2 + kb);
        }
        cp_commit();
    };

    uint32_t fph[NST] = {}, mph[NST] = {};
    fill(0);
    for (int i = 0; i < NCH; i++) {
        const int s = i & (NST - 1);
        cp_wait<0>();
        __syncthreads();
        if (tid == 0) { fence_async(); mbar_arrive_rank0(FULL0 + s * 8); }
        if (rank == 0 && tid == 0) {
            mbar_wait(FULL0 + s * 8, fph[s]); fph[s] ^= 1;
            const uint32_t st = sbase + 1024 + s * STAGE;
            uint64_t ahi = mk_desc(st + A_HI), alo = mk_desc(st + A_LO);
#pragma unroll
            for (int h = 0; h < 2; h++) {
                uint64_t bhi = mk_desc(st + B_HI + h * 16384);
                uint64_t blo = mk_desc(st + B_LO + h * 16384);
                uint32_t dh = tmem + h * 256;
#pragma unroll
                for (int kk = 0; kk < 4; kk++) {
                    uint32_t en = ((i > 0) || (kk > 0)) ? 1u : 0u;
                    mma_cg2(dh, ahi + kk * 2, bhi + kk * 2, en);
                    if (i < 64) {   // full chunks: lo corrections; ext chunks: hh only
                        mma_cg2(dh, alo + kk * 2, bhi + kk * 2, 1u);
                        mma_cg2(dh, ahi + kk * 2, blo + kk * 2, 1u);
                    }
                }
            }
            asm volatile("tcgen05.commit.cta_group::2.mbarrier::arrive::one.shared::cluster.multicast::cluster.b64 [%0], %1;"
                         :: "r"(MMAB0 + s * 8), "h"((uint16_t)3) : "memory");
        }
        const int j = i + 1;
        if (j < NCH) {
            const int s2 = j & (NST - 1);
            if (j >= NST) { mbar_wait(MMAB0 + s2 * 8, mph[s2]); mph[s2] ^= 1; }
            fill(j);
        }
    }
    mbar_wait(MMAB0 + SLAST * 8, FINPAR);
    asm volatile("tcgen05.fence::after_thread_sync;" ::: "memory");

    // epilogue
    {
        const int gm = arow0 + (wid & 3) * 32 + lane;
        float* crow = Cg + (size_t)gm * DOUT + n_tile * 512 + (wid >> 2) * 256;
        const uint32_t cb0 = tmem + (uint32_t)((wid >> 2) * 256);
#pragma unroll
        for (int cb = 0; cb < 256; cb += 32) {
            uint32_t d[32];
            asm volatile("tcgen05.ld.sync.aligned.32x32b.x32.b32 "
                "{%0,%1,%2,%3,%4,%5,%6,%7,%8,%9,%10,%11,%12,%13,%14,%15,"
                "%16,%17,%18,%19,%20,%21,%22,%23,%24,%25,%26,%27,%28,%29,%30,%31}, [%32];"
                : "=r"(d[0]),"=r"(d[1]),"=r"(d[2]),"=r"(d[3]),"=r"(d[4]),"=r"(d[5]),"=r"(d[6]),"=r"(d[7]),
                  "=r"(d[8]),"=r"(d[9]),"=r"(d[10]),"=r"(d[11]),"=r"(d[12]),"=r"(d[13]),"=r"(d[14]),"=r"(d[15]),
                  "=r"(d[16]),"=r"(d[17]),"=r"(d[18]),"=r"(d[19]),"=r"(d[20]),"=r"(d[21]),"=r"(d[22]),"=r"(d[23]),
                  "=r"(d[24]),"=r"(d[25]),"=r"(d[26]),"=r"(d[27]),"=r"(d[28]),"=r"(d[29]),"=r"(d[30]),"=r"(d[31])
                : "r"(cb0 + cb));
            asm volatile("tcgen05.wait::ld.sync.aligned;" ::: "memory");
#pragma unroll
            for (int c = 0; c < 32; c += 4)
                *reinterpret_cast<float4*>(crow + cb + c) =
                    make_float4(__uint_as_float(d[c]), __uint_as_float(d[c+1]),
                                __uint_as_float(d[c+2]), __uint_as_float(d[c+3]));
        }
    }
    __syncthreads();
    if (tid == 0) {
        for (int s = 0; s < NST; s++) { mbar_inval(FULL0 + s * 8); mbar_inval(MMAB0 + s * 8); }
    }
    __syncthreads();
    if (wid == 0) {
        asm volatile("tcgen05.relinquish_alloc_permit.cta_group::2.sync.aligned;");
        asm volatile("tcgen05.dealloc.cta_group::2.sync.aligned.b32 %0, %1;" :: "r"(tmem), "r"(512));
    }
    cluster_sync();
#endif
}

// ---------------------------------------------------------------- launch
// Inputs (metadata order): x, W, b, Wq, Wk, A, Bm
extern "C" void kernel_launch(void* const* d_in, const int* in_sizes, int n_in,
                              void* d_out, int out_size) {
    const float* x  = (const float*)d_in[0];
    const float* W  = (const float*)d_in[1];
    const float* b  = (const float*)d_in[2];
    const float* Wq = (const float*)d_in[3];
    const float* Wk = (const float*)d_in[4];
    const float* A  = (const float*)d_in[5];
    const float* Bm = (const float*)d_in[6];
    float* out = (float*)d_out;

    constexpr int SMEM0 = 1024 + 4 * 32768;    // 132096
    constexpr int SMEM1 = 1024 + 2 * 98304;    // 197632
    cudaFuncSetAttribute(gemm_proj_kernel, cudaFuncAttributeMaxDynamicSharedMemorySize, SMEM0);
    cudaFuncSetAttribute(gemm_main_kernel, cudaFuncAttributeMaxDynamicSharedMemorySize, SMEM1);

    // pre-split x and W into [hi|lo] bf16 panels (merged, ILP-optimized)
    split_xw_kernel  <<<MTOK + DOUT, 256>>>(x, W);
    split_proj_kernel<<<(int)(((size_t)NPROJ_PAD * DIN / 4 + 255) / 256), 256>>>(Wq, Wk, A);
    pack_b2_kernel   <<<(DOUT * GEXT + 255) / 256, 256>>>(Bm, b);

    // projections P = x_hi @ [Wq;Wk;A]_hi^T
    gemm_proj_kernel<<<dim3(2 * (NPROJ_PAD / 256), MTOK / 256), 256, SMEM0>>>();

    // routing -> G ext cols (hi only) of g_Xp
    routing_kernel<<<(MTOK * 32) / 256, 256>>>();

    // out = x @ W^T + G @ B2^T (+bias): dedup 3-product GEMM, hi-only ext chunks
    gemm_main_kernel<<<dim3(2 * (DOUT / 512), MTOK / 256), 256, SMEM1>>>(out);
}